// round 17
// baseline (speedup 1.0000x reference)
#include <cuda_runtime.h>

// EMA scan: out[b,t,d] = a*out[b,t-1,d] + (1-a)*x[b,t,d], out[b,-1,d]=0
// Shapes fixed: B=4, S=4096, D=2048, fp32.
//
// Single kernel, CTA owns 32 channels for the whole sequence (traffic
// floor: x read once, out written once = 268MB). Round-17 vs r12/r16:
//  - loads pre-scaled: w = om*x at load time (MUL hides under memory
//    latency) -> local scan is a PURE fma chain (minimum serial depth)
//  - local prefix kept in w[] -> store is one independent
//    fma(carry, alpha^(j+1), w[j]) per step (r16 algebra)
//  - carry weighted-sum with 2 accumulators (serial depth 8)
// CTA = 512 thr = 32 ch x 16 sub-chunks of LEN=16; 16 stages,
// 1 barrier/stage, parity-buffered smem, x2 ping-pong prefetch,
// __ldcs/__stcs. 256 CTAs, 2 CTAs/SM.

#define B 4
#define S 4096
#define D 2048
#define CH 32                  // channels per CTA
#define SC 16                  // sub-chunks per stage (== warps)
#define LEN 16                 // timesteps per sub-chunk
#define STAGE_T (SC * LEN)     // 256
#define NSTAGE (S / STAGE_T)   // 16 (even: required by the x2 unroll)
#define TPB (CH * SC)          // 512

constexpr float ALPHA = 0.99f;
constexpr float ONEM  = 0.01f;

__host__ __device__ constexpr float pow_alpha(int n) {
    double r = 1.0;
    for (int i = 0; i < n; ++i) r *= 0.99;
    return (float)r;
}

// DECP[i] = alpha^(LEN*i)
__constant__ float DECP[SC] = {
    pow_alpha(0),   pow_alpha(16),  pow_alpha(32),  pow_alpha(48),
    pow_alpha(64),  pow_alpha(80),  pow_alpha(96),  pow_alpha(112),
    pow_alpha(128), pow_alpha(144), pow_alpha(160), pow_alpha(176),
    pow_alpha(192), pow_alpha(208), pow_alpha(224), pow_alpha(240)
};

// PW[j] = alpha^(j+1): weight of the incoming carry at step j.
__constant__ float PW[LEN] = {
    pow_alpha(1),  pow_alpha(2),  pow_alpha(3),  pow_alpha(4),
    pow_alpha(5),  pow_alpha(6),  pow_alpha(7),  pow_alpha(8),
    pow_alpha(9),  pow_alpha(10), pow_alpha(11), pow_alpha(12),
    pow_alpha(13), pow_alpha(14), pow_alpha(15), pow_alpha(16)
};

// One stage: prefetch next tile pre-scaled by om into WN; pure-fma local
// scan keeping the prefix in W; carry exchange (compile-time parity P);
// independent correction + store.
#define STAGE_BODY(P, W, WN, xn, op, do_pf)                                \
    {                                                                      \
        if (do_pf) {                                                       \
            _Pragma("unroll")                                              \
            for (int j = 0; j < LEN; ++j)                                  \
                WN[j] = ONEM * __ldcs(&(xn)[(size_t)j * D]);               \
        }                                                                  \
        float e = 0.0f;                                                    \
        _Pragma("unroll")                                                  \
        for (int j = 0; j < LEN; ++j) {                                    \
            e = fmaf(ALPHA, e, W[j]);                                      \
            W[j] = e;          /* keep local prefix */                     \
        }                                                                  \
        s_ends[P][sc][ch] = e;                                             \
        __syncthreads();                                                   \
        float acc0 = DECP[sc] * s_carry[P][ch];                            \
        float acc1 = 0.0f;                                                 \
        _Pragma("unroll")                                                  \
        for (int i = 0; i < SC - 1; i += 2) {                              \
            const int i0 = sc - 1 - i;                                     \
            const float w0 = (i0 >= 0) ? DECP[i0] : 0.0f;                  \
            acc0 = fmaf(w0, s_ends[P][i][ch], acc0);                       \
            if (i + 1 < SC - 1) {                                          \
                const int i1 = sc - 2 - i;                                 \
                const float w1 = (i1 >= 0) ? DECP[i1] : 0.0f;              \
                acc1 = fmaf(w1, s_ends[P][i + 1][ch], acc1);               \
            }                                                              \
        }                                                                  \
        const float carry = acc0 + acc1;                                   \
        if (sc == SC - 1)                                                  \
            s_carry[(P) ^ 1][ch] = fmaf(DECP[1], carry, e);                \
        _Pragma("unroll")                                                  \
        for (int j = 0; j < LEN; ++j)                                      \
            __stcs(&(op)[(size_t)j * D], fmaf(carry, PW[j], W[j]));        \
    }

__global__ void __launch_bounds__(TPB, 2)
ema_cta(const float* __restrict__ x, float* __restrict__ out) {
    __shared__ float s_ends[2][SC][CH];   // parity-buffered sub-chunk ends
    __shared__ float s_carry[2][CH];      // parity-buffered stage carry

    const int tid = threadIdx.x;
    const int ch = tid & (CH - 1);
    const int sc = tid >> 5;              // warp id == sub-chunk id (uniform)
    const int d = blockIdx.x * CH + ch;
    const int b = blockIdx.y;

    if (tid < CH) s_carry[0][tid] = 0.0f;   // ordered by stage-0 barrier

    // This thread's sub-chunk column base (stage 0); advance by constant.
    const size_t col = (size_t)b * S * D + (size_t)sc * LEN * D + d;
    const float* xp = x + col;
    float* op = out + col;
    const size_t STRIDE = (size_t)STAGE_T * D;

    float w0[LEN], w1[LEN];
#pragma unroll
    for (int j = 0; j < LEN; ++j)
        w0[j] = ONEM * __ldcs(&xp[(size_t)j * D]);

#pragma unroll 1
    for (int st = 0; st < NSTAGE; st += 2) {
        // Stage st (parity 0): consume w0, prefetch w1.
        STAGE_BODY(0, w0, w1, xp + STRIDE, op, true)
        xp += STRIDE; op += STRIDE;

        // Stage st+1 (parity 1): consume w1, prefetch w0 (skip on last).
        const bool pf = (st + 2 < NSTAGE);
        STAGE_BODY(1, w1, w0, xp + STRIDE, op, pf)
        xp += STRIDE; op += STRIDE;
    }
}

extern "C" void kernel_launch(void* const* d_in, const int* in_sizes, int n_in,
                              void* d_out, int out_size) {
    const float* x = (const float*)d_in[0];
    float* out = (float*)d_out;

    dim3 grid(D / CH, B);   // (64, 4) = 256 CTAs
    ema_cta<<<grid, TPB>>>(x, out);
}